// round 2
// baseline (speedup 1.0000x reference)
#include <cuda_runtime.h>

#define BSZ  4
#define CDIM 256
#define NPIX 4096
#define CQD  32
#define ATTN_SCALE (1.0f/64.0f)   // 1/sqrt(4096)

// ---------------- scratch (device globals: allocation-free) ----------------
__device__ float g_q[BSZ*NPIX*CQD];    // [b][n][cq]
__device__ float g_k[BSZ*NPIX*CQD];    // [b][n][cq]  (K^T layout)
__device__ float g_v[BSZ*NPIX*CDIM];   // [b][n][c]
__device__ float g_m[BSZ*NPIX];
__device__ float g_l[BSZ*NPIX];

// ---------------- packed f32x2 helpers ----------------
__device__ __forceinline__ void fma2acc(unsigned long long &d,
                                        unsigned long long a,
                                        unsigned long long b) {
    asm("fma.rn.f32x2 %0, %1, %2, %0;" : "+l"(d) : "l"(a), "l"(b));
}
__device__ __forceinline__ unsigned long long packf2(float x, float y) {
    unsigned long long u;
    asm("mov.b64 %0, {%1,%2};" : "=l"(u) : "f"(x), "f"(y));
    return u;
}
__device__ __forceinline__ float2 unpackf2(unsigned long long u) {
    float2 v;
    asm("mov.b64 {%0,%1}, %2;" : "=f"(v.x), "=f"(v.y) : "l"(u));
    return v;
}

// ============================================================================
// Kernel 1: fused QKV projection.
// Out[b][n][j] = sum_c Wall[j][c] * x[b][c][n] + ball[j],  j in [0,320)
// j<32 -> Q, j<64 -> K, else -> V. Tiled GEMM: 128 pixels x 64 j per block.
// ============================================================================
__global__ __launch_bounds__(256) void qkv_kernel(
    const float* __restrict__ x,
    const float* __restrict__ Wq, const float* __restrict__ bq,
    const float* __restrict__ Wk, const float* __restrict__ bk,
    const float* __restrict__ Wv, const float* __restrict__ bv)
{
    __shared__ __align__(16) float Xs[32*128];   // [k][pixel]
    __shared__ __align__(16) float Ws[32*68];    // [k][j] padded

    const int t  = threadIdx.x;
    const int tm = t & 31;        // pixel group
    const int tj = t >> 5;        // j group (0..7), constant per warp
    const int n0 = blockIdx.x * 128;
    const int j0 = blockIdx.y * 64;
    const int b  = blockIdx.z;

    // W-load duty: thread owns row jj, 8 consecutive k at kkb
    const int jj  = t >> 2;        // 0..63
    const int kkb = (t & 3) * 8;   // 0,8,16,24
    const int jglob = j0 + jj;
    const float* Wrow;
    if (jglob < 32)      Wrow = Wq + (size_t)jglob * CDIM;
    else if (jglob < 64) Wrow = Wk + (size_t)(jglob - 32) * CDIM;
    else                 Wrow = Wv + (size_t)(jglob - 64) * CDIM;

    float acc[4][8];
    #pragma unroll
    for (int i = 0; i < 4; i++)
        #pragma unroll
        for (int u = 0; u < 8; u++) acc[i][u] = 0.0f;

    for (int kc = 0; kc < CDIM; kc += 32) {
        // Load X tile: 32 rows x 128 pixels (1024 float4)
        #pragma unroll
        for (int i = 0; i < 4; i++) {
            int f   = t + i * 256;
            int row = f >> 5, c4 = f & 31;
            ((float4*)Xs)[f] =
                ((const float4*)(x + ((size_t)(b*CDIM + kc + row))*NPIX + n0))[c4];
        }
        // Load W tile transposed: Ws[k][j]
        #pragma unroll
        for (int u = 0; u < 8; u += 4) {
            float4 w = *((const float4*)(Wrow + kc + kkb + u));
            Ws[(kkb+u+0)*68 + jj] = w.x;
            Ws[(kkb+u+1)*68 + jj] = w.y;
            Ws[(kkb+u+2)*68 + jj] = w.z;
            Ws[(kkb+u+3)*68 + jj] = w.w;
        }
        __syncthreads();
        #pragma unroll
        for (int kk = 0; kk < 32; kk++) {
            float4 a  = *(const float4*)&Xs[kk*128 + tm*4];
            float4 w0 = *(const float4*)&Ws[kk*68 + tj*8];
            float4 w1 = *(const float4*)&Ws[kk*68 + tj*8 + 4];
            float av[4] = {a.x, a.y, a.z, a.w};
            float wv[8] = {w0.x, w0.y, w0.z, w0.w, w1.x, w1.y, w1.z, w1.w};
            #pragma unroll
            for (int i = 0; i < 4; i++)
                #pragma unroll
                for (int u = 0; u < 8; u++)
                    acc[i][u] = fmaf(av[i], wv[u], acc[i][u]);
        }
        __syncthreads();
    }

    // Epilogue: scatter into Q / K^T / V with bias
    #pragma unroll
    for (int u = 0; u < 8; u++) {
        int j = j0 + tj*8 + u;
        float bias = (j < 32) ? bq[j] : ((j < 64) ? bk[j-32] : bv[j-64]);
        #pragma unroll
        for (int i = 0; i < 4; i++) {
            int n = n0 + tm*4 + i;
            size_t bn = (size_t)(b*NPIX + n);
            float val = acc[i][u] + bias;
            if (j < 32)      g_q[bn*CQD + j]        = val;
            else if (j < 64) g_k[bn*CQD + (j-32)]   = val;
            else             g_v[bn*CDIM + (j-64)]  = val;
        }
    }
}

// ============================================================================
// Kernel 2: softmax stats (row max m, denominator l) for 64 rows per block.
// 4 threads per row; q row register-resident; f32x2 dots; shfl combine.
// ============================================================================
__global__ __launch_bounds__(256) void stats_kernel()
{
    __shared__ __align__(16) float Ks[128*36];  // [key][d] padded to 36
    const int t   = threadIdx.x;
    const int b   = blockIdx.y;
    const int n0  = blockIdx.x * 64;
    const int row = t >> 2;       // 0..63
    const int sub = t & 3;

    unsigned long long qp[16];
    {
        const float4* qptr = (const float4*)(g_q + ((size_t)(b*NPIX + n0 + row))*CQD);
        #pragma unroll
        for (int i = 0; i < 8; i++) {
            float4 q4 = qptr[i];
            qp[2*i]   = packf2(q4.x, q4.y);
            qp[2*i+1] = packf2(q4.z, q4.w);
        }
    }

    float m = -1e30f, l = 0.0f;
    for (int key0 = 0; key0 < NPIX; key0 += 128) {
        __syncthreads();
        #pragma unroll
        for (int i = 0; i < 16; i++) {
            int f = t + i*256;
            int key = f >> 5, d = f & 31;
            Ks[key*36 + d] = g_k[((size_t)(b*NPIX + key0 + key))*CQD + d];
        }
        __syncthreads();

        float sv[32];
        #pragma unroll
        for (int i = 0; i < 32; i++) {
            int key = sub + i*4;
            unsigned long long s2 = 0ull;
            #pragma unroll
            for (int d4 = 0; d4 < 8; d4++) {
                ulonglong2 kp = *(const ulonglong2*)&Ks[key*36 + d4*4];
                fma2acc(s2, qp[2*d4],   kp.x);
                fma2acc(s2, qp[2*d4+1], kp.y);
            }
            float2 sf = unpackf2(s2);
            sv[i] = (sf.x + sf.y) * ATTN_SCALE;
        }
        float tmax = m;
        #pragma unroll
        for (int i = 0; i < 32; i++) tmax = fmaxf(tmax, sv[i]);
        l *= __expf(m - tmax);
        #pragma unroll
        for (int i = 0; i < 32; i++) l += __expf(sv[i] - tmax);
        m = tmax;
    }

    // combine 4 partials per row (lanes are consecutive groups of 4)
    #pragma unroll
    for (int off = 1; off < 4; off <<= 1) {
        float mo = __shfl_xor_sync(0xffffffffu, m, off);
        float lo = __shfl_xor_sync(0xffffffffu, l, off);
        float mn = fmaxf(m, mo);
        l = l * __expf(m - mn) + lo * __expf(mo - mn);
        m = mn;
    }
    if (sub == 0) {
        g_m[b*NPIX + n0 + row] = m;
        g_l[b*NPIX + n0 + row] = l;
    }
}

// ============================================================================
// Kernel 3: output. Per block: 64 query rows x full C=256.
// Sweep key tiles of 64: recompute S, p = exp(s - m) into smem (transposed),
// O += P @ V with packed f32x2 FMAs. Epilogue scales by 1/l.
// smem: Qs 64x36, Ks 64x36, Ps 64x68 (key-major), Vs 64x256  = 101376 B
// ============================================================================
#define SM3_BYTES 101376

__global__ __launch_bounds__(256) void out_kernel(float* __restrict__ out)
{
    extern __shared__ __align__(16) float sm[];
    float* Qs = sm;            // 64*36 = 2304
    float* Ks = sm + 2304;     // 64*36 = 2304
    float* Ps = sm + 4608;     // 64*68 = 4352   Ps[key][row]
    float* Vs = sm + 8960;     // 64*256 = 16384

    const int t     = threadIdx.x;
    const int b     = blockIdx.y;
    const int n0    = blockIdx.x * 64;
    const int tc    = t & 15;       // c-quad group
    const int trow  = t >> 4;       // 0..15 -> rows trow*4..+3
    const int srow  = t & 63;       // row for S compute
    const int skgrp = t >> 6;       // key group for S compute

    // Load Q tile
    #pragma unroll
    for (int i = 0; i < 8; i++) {
        int f = t + i*256;
        int row = f >> 5, d = f & 31;
        Qs[row*36 + d] = g_q[((size_t)(b*NPIX + n0 + row))*CQD + d];
    }
    __syncthreads();

    // Pack this thread's q row (for S phase)
    unsigned long long qp[16];
    #pragma unroll
    for (int d4 = 0; d4 < 8; d4++) {
        float4 q4 = *(const float4*)&Qs[srow*36 + d4*4];
        qp[2*d4]   = packf2(q4.x, q4.y);
        qp[2*d4+1] = packf2(q4.z, q4.w);
    }
    const float mrow = g_m[b*NPIX + n0 + srow];

    unsigned long long o2[4][8];
    #pragma unroll
    for (int r = 0; r < 4; r++)
        #pragma unroll
        for (int u = 0; u < 8; u++) o2[r][u] = 0ull;

    for (int key0 = 0; key0 < NPIX; key0 += 64) {
        __syncthreads();   // previous tile's P/V fully consumed
        // Load K tile
        #pragma unroll
        for (int i = 0; i < 8; i++) {
            int f = t + i*256;
            int key = f >> 5, d = f & 31;
            Ks[key*36 + d] = g_k[((size_t)(b*NPIX + key0 + key))*CQD + d];
        }
        // Load V tile (contiguous 64KB copy)
        const float4* vsrc = (const float4*)(g_v + ((size_t)(b*NPIX + key0))*CDIM);
        #pragma unroll
        for (int i = 0; i < 16; i++)
            ((float4*)Vs)[t + i*256] = vsrc[t + i*256];
        __syncthreads();

        // S + exp -> Ps[key][row]
        #pragma unroll
        for (int i = 0; i < 16; i++) {
            int key = skgrp*16 + i;
            unsigned long long s2 = 0ull;
            #pragma unroll
            for (int d4 = 0; d4 < 8; d4++) {
                ulonglong2 kp = *(const ulonglong2*)&Ks[key*36 + d4*4];
                fma2acc(s2, qp[2*d4],   kp.x);
                fma2acc(s2, qp[2*d4+1], kp.y);
            }
            float2 sf = unpackf2(s2);
            Ps[key*68 + srow] = __expf((sf.x + sf.y)*ATTN_SCALE - mrow);
        }
        __syncthreads();

        // O += P @ V   (packed f32x2)
        #pragma unroll 8
        for (int kk = 0; kk < 64; kk++) {
            float4 p4 = *(const float4*)&Ps[kk*68 + trow*4];
            unsigned long long pp0 = packf2(p4.x, p4.x);
            unsigned long long pp1 = packf2(p4.y, p4.y);
            unsigned long long pp2 = packf2(p4.z, p4.z);
            unsigned long long pp3 = packf2(p4.w, p4.w);
            #pragma unroll
            for (int seg = 0; seg < 4; seg++) {
                ulonglong2 v2 = *(const ulonglong2*)&Vs[kk*256 + seg*64 + tc*4];
                fma2acc(o2[0][seg*2],   pp0, v2.x);
                fma2acc(o2[0][seg*2+1], pp0, v2.y);
                fma2acc(o2[1][seg*2],   pp1, v2.x);
                fma2acc(o2[1][seg*2+1], pp1, v2.y);
                fma2acc(o2[2][seg*2],   pp2, v2.x);
                fma2acc(o2[2][seg*2+1], pp2, v2.y);
                fma2acc(o2[3][seg*2],   pp3, v2.x);
                fma2acc(o2[3][seg*2+1], pp3, v2.y);
            }
        }
    }

    // Epilogue: scale by 1/l, write out[b][n][c] (raw [B,N,C] layout)
    #pragma unroll
    for (int r = 0; r < 4; r++) {
        int n = n0 + trow*4 + r;
        float linv = 1.0f / g_l[b*NPIX + n];
        float* orow = out + ((size_t)(b*NPIX + n))*CDIM;
        #pragma unroll
        for (int seg = 0; seg < 4; seg++) {
            float2 a = unpackf2(o2[r][seg*2]);
            float2 c = unpackf2(o2[r][seg*2+1]);
            float4 val = make_float4(a.x*linv, a.y*linv, c.x*linv, c.y*linv);
            *(float4*)&orow[seg*64 + tc*4] = val;
        }
    }
}

// ============================================================================
extern "C" void kernel_launch(void* const* d_in, const int* in_sizes, int n_in,
                              void* d_out, int out_size)
{
    const float* x  = (const float*)d_in[0];
    const float* Wq = (const float*)d_in[1];
    const float* bq = (const float*)d_in[2];
    const float* Wk = (const float*)d_in[3];
    const float* bk = (const float*)d_in[4];
    const float* Wv = (const float*)d_in[5];
    const float* bv = (const float*)d_in[6];
    float* out = (float*)d_out;

    cudaFuncSetAttribute(out_kernel,
                         cudaFuncAttributeMaxDynamicSharedMemorySize, SM3_BYTES);

    qkv_kernel<<<dim3(32, 5, 4), 256>>>(x, Wq, bq, Wk, bk, Wv, bv);
    stats_kernel<<<dim3(64, 4), 256>>>();
    out_kernel<<<dim3(64, 4), 256, SM3_BYTES>>>(out);
}